// round 15
// baseline (speedup 1.0000x reference)
#include <cuda_runtime.h>
#include <cuda_fp16.h>
#include <cstdint>

#define NS 50000
#define NT 50000
#define NN 100000
#define DD 128
#define CAP 2200000
#define NB  ((NN + 255) / 256)

// ---------------- scratch (device globals: no runtime allocation) ----------------
static __device__ __half g_xh[NN * DD];   // transformed features, fp16 (gather source)
static __device__ float g_agg[NN * DD];   // rows [0,NS): conv2 agg; [NS,NN): conv1
static __device__ float g_sc [4 * NN];    // as1 | ad1 | as2 | ad2
static __device__ float g_wv [4 * DD];
static __device__ int   g_degflag[NN + 512];  // [0,NN): degree; [NN,..): lookback flags
static __device__ int   g_rowptr[NN];
static __device__ int   g_cur[NN];
static __device__ int   g_blk_agg[NB + 1];
static __device__ int   g_blk_pref[NB + 1];
static __device__ int   g_esrc[CAP];
static __device__ float g_ew  [CAP];

#define MMA_F16(d, a0, a1, a2, a3, b0, b1)                                       \
    asm volatile("mma.sync.aligned.m16n8k16.row.col.f32.f16.f16.f32 "            \
        "{%0,%1,%2,%3}, {%4,%5,%6,%7}, {%8,%9}, {%0,%1,%2,%3};"                  \
        : "+f"((d)[0]), "+f"((d)[1]), "+f"((d)[2]), "+f"((d)[3])                 \
        : "r"(a0), "r"(a1), "r"(a2), "r"(a3), "r"(b0), "r"(b1))

#define LDSM_X4(r0, r1, r2, r3, addr)                                            \
    asm volatile("ldmatrix.sync.aligned.m8n8.x4.shared.b16 {%0,%1,%2,%3}, [%4];" \
        : "=r"(r0), "=r"(r1), "=r"(r2), "=r"(r3) : "r"(addr))

// =============== GEMM: C = A[M,128] @ W[128,128]^T, 1-pass fp16 + ldmatrix =======
// 64-row tile / 256 threads / 8 warps (4 m-tiles x 2 n-halves).
// A, W single fp16 rounding; fp32 accumulate. smem 52KB -> 4 CTAs/SM.
// Dual-segment grid; doScores=1: +bias, fp16->g_xh, fused scores. else relu->C.
#define PH 136
__global__ __launch_bounds__(256)
void mma_gemm(const float* __restrict__ A1, const float* __restrict__ W1p,
              const float* __restrict__ b1, float* __restrict__ C1, int M1, int so1,
              const float* __restrict__ A2, const float* __restrict__ W2p,
              const float* __restrict__ b2, float* __restrict__ C2, int M2, int so2,
              int nb1, int doRelu, int doScores)
{
    extern __shared__ __half sh[];
    __half* sA = sh;               // 64  x PH
    __half* sW = sh + 64 * PH;     // 128 x PH

    const float* A; const float* W; const float* bias; float* C;
    int M, scoreOff, row0;
    if (blockIdx.x < nb1) {
        A = A1; W = W1p; bias = b1; C = C1; M = M1; scoreOff = so1;
        row0 = blockIdx.x * 64;
    } else {
        A = A2; W = W2p; bias = b2; C = C2; M = M2; scoreOff = so2;
        row0 = (blockIdx.x - nb1) * 64;
    }
    const int tid = threadIdx.x;

    for (int i = tid; i < 4096; i += 256) {
        int n  = i >> 5;
        int k4 = (i & 31) << 2;
        float4 w = *(const float4*)(W + n * 128 + k4);
        uint2 p;
        *(__half2*)&p.x = __floats2half2_rn(w.x, w.y);
        *(__half2*)&p.y = __floats2half2_rn(w.z, w.w);
        *(uint2*)(sW + n * PH + k4) = p;
    }
    for (int i = tid; i < 2048; i += 256) {
        int r  = i >> 5;
        int k4 = (i & 31) << 2;
        int gr = row0 + r;
        float4 v = make_float4(0.f, 0.f, 0.f, 0.f);
        if (gr < M) v = *(const float4*)(A + (size_t)gr * 128 + k4);
        uint2 p;
        *(__half2*)&p.x = __floats2half2_rn(v.x, v.y);
        *(__half2*)&p.y = __floats2half2_rn(v.z, v.w);
        *(uint2*)(sA + r * PH + k4) = p;
    }
    __syncthreads();

    const int wid  = tid >> 5;
    const int lane = tid & 31;
    const int mw   = wid & 3;
    const int nb   = (wid >> 2) * 64;
    const int g    = lane >> 2;
    const int tq   = lane & 3;

    // per-lane ldmatrix base addresses (shared space, bytes)
    const int r8 = lane & 7;
    const int j  = lane >> 3;
    const uint32_t aBase = (uint32_t)__cvta_generic_to_shared(sA)
        + (uint32_t)(((mw * 16 + ((j & 1) << 3) + r8) * PH + ((j >> 1) << 3)) * 2);
    const uint32_t bBase = (uint32_t)__cvta_generic_to_shared(sW)
        + (uint32_t)(((nb + ((j >> 1) << 3) + r8) * PH + ((j & 1) << 3)) * 2);

    float acc[8][4] = {};

#pragma unroll
    for (int ks = 0; ks < 8; ks++) {
        uint32_t a0, a1, a2, a3;
        LDSM_X4(a0, a1, a2, a3, aBase + ks * 32);
        uint32_t b[16];
#pragma unroll
        for (int p = 0; p < 4; p++)
            LDSM_X4(b[p * 4], b[p * 4 + 1], b[p * 4 + 2], b[p * 4 + 3],
                    bBase + (uint32_t)(p * 16 * PH * 2) + ks * 32);
#pragma unroll
        for (int nt = 0; nt < 8; nt++)
            MMA_F16(acc[nt], a0, a1, a2, a3, b[nt * 2], b[nt * 2 + 1]);
    }

    const int r0 = row0 + mw * 16 + g;
    const int r1 = r0 + 8;
    float s0[4] = {}, s1[4] = {};

#pragma unroll
    for (int nt = 0; nt < 8; nt++) {
        int c = nb + nt * 8 + tq * 2;
        float bx = 0.f, by = 0.f;
        if (bias) { float2 b = *(const float2*)(bias + c); bx = b.x; by = b.y; }
        float o00 = acc[nt][0] + bx, o01 = acc[nt][1] + by;
        float o10 = acc[nt][2] + bx, o11 = acc[nt][3] + by;
        if (doScores) {
#pragma unroll
            for (int t = 0; t < 4; t++) {
                float2 w = *(const float2*)(g_wv + t * 128 + c);
                s0[t] += o00 * w.x + o01 * w.y;
                s1[t] += o10 * w.x + o11 * w.y;
            }
            if (r0 < M) *(__half2*)(g_xh + (size_t)(scoreOff + r0) * 128 + c) =
                __floats2half2_rn(o00, o01);
            if (r1 < M) *(__half2*)(g_xh + (size_t)(scoreOff + r1) * 128 + c) =
                __floats2half2_rn(o10, o11);
        } else {
            if (doRelu) {
                o00 = o00 > 0.f ? o00 : 0.f; o01 = o01 > 0.f ? o01 : 0.f;
                o10 = o10 > 0.f ? o10 : 0.f; o11 = o11 > 0.f ? o11 : 0.f;
            }
            if (r0 < M) *(float2*)(C + (size_t)r0 * 128 + c) = make_float2(o00, o01);
            if (r1 < M) *(float2*)(C + (size_t)r1 * 128 + c) = make_float2(o10, o11);
        }
    }

    if (doScores) {
#pragma unroll
        for (int t = 0; t < 4; t++) {
            s0[t] += __shfl_xor_sync(0xFFFFFFFFu, s0[t], 1);
            s0[t] += __shfl_xor_sync(0xFFFFFFFFu, s0[t], 2);
            s1[t] += __shfl_xor_sync(0xFFFFFFFFu, s1[t], 1);
            s1[t] += __shfl_xor_sync(0xFFFFFFFFu, s1[t], 2);
        }
        if (tq == 0) {
#pragma unroll
            for (int t = 0; t < 4; t++) {
                if (r0 < M) atomicAdd(&g_sc[t * NN + scoreOff + r0], s0[t]);
                if (r1 < M) atomicAdd(&g_sc[t * NN + scoreOff + r1], s1[t]);
            }
        }
    }
}

// ---------------- precompute wv = W^T a (4 vectors of 128) -----------------------
__global__ void wvec_k(const float* __restrict__ W1, const float* __restrict__ a1s,
                       const float* __restrict__ a1d,
                       const float* __restrict__ W2, const float* __restrict__ a2s,
                       const float* __restrict__ a2d)
{
    int d = threadIdx.x;
    float s1 = 0.f, s2 = 0.f, s3 = 0.f, s4 = 0.f;
    for (int k = 0; k < 128; k++) {
        float w1 = W1[k * 128 + d], w2 = W2[k * 128 + d];
        s1 += w1 * a1s[k];
        s2 += w1 * a1d[k];
        s3 += w2 * a2s[k];
        s4 += w2 * a2d[k];
    }
    g_wv[d] = s1; g_wv[128 + d] = s2; g_wv[256 + d] = s3; g_wv[384 + d] = s4;
}

__device__ __forceinline__ float leaky(float e) { return e > 0.f ? e : 0.2f * e; }

// ---------------- combined edge decomposition ------------------------------------
__device__ __forceinline__ bool decomp_edge(int i, const int* edge, const int* paper,
                                            const int* author, int E, int Ep, int Ea,
                                            int& s, int& d, int& conv1)
{
    if (i < E) { s = edge[i]; d = edge[E + i] + NS; conv1 = 1; return true; }
    i -= E;
    if (i < Ea) { s = author[i]; d = author[Ea + i]; conv1 = 1; return d >= NS; }
    i -= Ea;
    if (i < NT) { s = d = NS + i; conv1 = 1; return true; }
    i -= NT;
    if (i < E) { s = edge[E + i] + NS; d = edge[i]; conv1 = 0; return true; }
    i -= E;
    if (i < Ep) { s = paper[i]; d = paper[Ep + i]; conv1 = 0; return d < NS; }
    i -= Ep;
    if (i < NS) { s = d = i; conv1 = 0; return true; }
    return false;
}

__global__ void hist_k(const int* __restrict__ edge, const int* __restrict__ paper,
                       const int* __restrict__ author, int E, int Ep, int Ea, int T)
{
    int i = blockIdx.x * blockDim.x + threadIdx.x;
    if (i >= T) return;
    int s, d, c1;
    if (decomp_edge(i, edge, paper, author, E, Ep, Ea, s, d, c1))
        atomicAdd(&g_degflag[d], 1);
}

// ---------------- single-kernel decoupled-lookback exclusive scan ----------------
__global__ __launch_bounds__(256)
void scan_k()
{
    __shared__ int sm[256];
    __shared__ int s_prefix;
    int* flag = g_degflag + NN;
    const int b = blockIdx.x, t = threadIdx.x;
    const int i = b * 256 + t;
    int v = (i < NN) ? g_degflag[i] : 0;
    sm[t] = v; __syncthreads();
#pragma unroll
    for (int off = 1; off < 256; off <<= 1) {
        int u = (t >= off) ? sm[t - off] : 0;
        __syncthreads();
        sm[t] += u;
        __syncthreads();
    }
    int incl  = sm[t];
    int total = sm[255];

    if (t == 0) {
        g_blk_agg[b] = total;
        __threadfence();
        atomicExch(&flag[b], 1);
        int prefix = 0;
        for (int jj = b - 1; jj >= 0; ) {
            int f;
            do { f = atomicAdd(&flag[jj], 0); } while (f == 0);
            if (f == 2) { prefix += g_blk_pref[jj]; break; }
            prefix += g_blk_agg[jj];
            jj--;
        }
        g_blk_pref[b] = prefix + total;
        __threadfence();
        atomicExch(&flag[b], 2);
        s_prefix = prefix;
    }
    __syncthreads();
    if (i < NN) {
        int rp = s_prefix + incl - v;
        g_rowptr[i] = rp;
        g_cur[i]    = rp;
    }
}

__global__ void fill_k(const int* __restrict__ edge, const int* __restrict__ paper,
                       const int* __restrict__ author, int E, int Ep, int Ea, int T)
{
    int i = blockIdx.x * blockDim.x + threadIdx.x;
    if (i >= T) return;
    int s, d, c1;
    if (!decomp_edge(i, edge, paper, author, E, Ep, Ea, s, d, c1)) return;
    float e = c1 ? (g_sc[s] + g_sc[NN + d]) : (g_sc[2 * NN + s] + g_sc[3 * NN + d]);
    float w = __expf(leaky(e));
    int pos = atomicAdd(&g_cur[d], 1);
    if (pos < CAP) { g_esrc[pos] = s; g_ew[pos] = w; }
}

// ---------------- SpMM: warp per dst row, shfl-broadcast edges, ILP-4 gathers ----
__device__ __forceinline__ void gacc(float4& acc, float w, uint2 u)
{
    float2 f0 = __half22float2(*(__half2*)&u.x);
    float2 f1 = __half22float2(*(__half2*)&u.y);
    acc.x += w * f0.x; acc.y += w * f0.y;
    acc.z += w * f1.x; acc.w += w * f1.y;
}

__global__ __launch_bounds__(256)
void spmm_k()
{
    int r    = (blockIdx.x * blockDim.x + threadIdx.x) >> 5;
    int lane = threadIdx.x & 31;
    if (r >= NN) return;
    int start = g_rowptr[r];
    int n     = g_degflag[r];
    float4 acc = make_float4(0.f, 0.f, 0.f, 0.f);
    float  den = 0.f;

    for (int base = 0; base < n; base += 32) {
        int m = n - base; if (m > 32) m = 32;
        int   src = 0; float wv = 0.f;
        if (lane < m) {
            src = g_esrc[start + base + lane];
            wv  = g_ew  [start + base + lane];
        }
        int jj = 0;
        for (; jj + 4 <= m; jj += 4) {
            int   s0 = __shfl_sync(0xFFFFFFFFu, src, jj);
            int   s1 = __shfl_sync(0xFFFFFFFFu, src, jj + 1);
            int   s2 = __shfl_sync(0xFFFFFFFFu, src, jj + 2);
            int   s3 = __shfl_sync(0xFFFFFFFFu, src, jj + 3);
            float w0 = __shfl_sync(0xFFFFFFFFu, wv, jj);
            float w1 = __shfl_sync(0xFFFFFFFFu, wv, jj + 1);
            float w2 = __shfl_sync(0xFFFFFFFFu, wv, jj + 2);
            float w3 = __shfl_sync(0xFFFFFFFFu, wv, jj + 3);
            uint2 u0 = *(const uint2*)(g_xh + (size_t)s0 * 128 + lane * 4);
            uint2 u1 = *(const uint2*)(g_xh + (size_t)s1 * 128 + lane * 4);
            uint2 u2 = *(const uint2*)(g_xh + (size_t)s2 * 128 + lane * 4);
            uint2 u3 = *(const uint2*)(g_xh + (size_t)s3 * 128 + lane * 4);
            gacc(acc, w0, u0); gacc(acc, w1, u1);
            gacc(acc, w2, u2); gacc(acc, w3, u3);
            den += w0 + w1 + w2 + w3;
        }
        for (; jj < m; jj++) {
            int   s0 = __shfl_sync(0xFFFFFFFFu, src, jj);
            float w0 = __shfl_sync(0xFFFFFFFFu, wv, jj);
            uint2 u0 = *(const uint2*)(g_xh + (size_t)s0 * 128 + lane * 4);
            gacc(acc, w0, u0);
            den += w0;
        }
    }
    float rc = __frcp_rn(den + 1e-16f);
    acc.x *= rc; acc.y *= rc; acc.z *= rc; acc.w *= rc;
    *(float4*)(g_agg + (size_t)r * 128 + lane * 4) = acc;
}

// ---------------- host launch -----------------------------------------------------
extern "C" void kernel_launch(void* const* d_in, const int* in_sizes, int n_in,
                              void* d_out, int out_size)
{
    const int* edge   = (const int*)d_in[0];
    const int* paper  = (const int*)d_in[1];
    const int* author = (const int*)d_in[2];
    const float* x_s = (const float*)d_in[3];
    const float* x_t = (const float*)d_in[4];
    const float* Ws  = (const float*)d_in[5];
    const float* bs  = (const float*)d_in[6];
    const float* Wt  = (const float*)d_in[7];
    const float* bt  = (const float*)d_in[8];
    const float* W1  = (const float*)d_in[9];
    const float* a1s = (const float*)d_in[10];
    const float* a1d = (const float*)d_in[11];
    const float* W2  = (const float*)d_in[12];
    const float* a2s = (const float*)d_in[13];
    const float* a2d = (const float*)d_in[14];

    const int E  = in_sizes[0] / 2;
    const int Ep = in_sizes[1] / 2;
    const int Ea = in_sizes[2] / 2;
    const int T  = 2 * E + Ea + Ep + NS + NT;

    float *pagg, *psc;
    cudaGetSymbolAddress((void**)&pagg, g_agg);
    cudaGetSymbolAddress((void**)&psc,  g_sc);
    int* pdegflag;
    cudaGetSymbolAddress((void**)&pdegflag, g_degflag);

    float* out = (float*)d_out;
    float* out_s = out;                     // conv2 result rows [0, NS)
    float* out_t = out + (size_t)NS * DD;   // conv1 result rows [NS, NN)

    const int GEMM_SMEM = (64 * PH + 128 * PH) * 2;  // 52224 B -> 4 CTAs/SM
    cudaFuncSetAttribute((const void*)mma_gemm,
                         cudaFuncAttributeMaxDynamicSharedMemorySize, GEMM_SMEM);

    cudaStream_t s2;
    cudaStreamCreateWithFlags(&s2, cudaStreamNonBlocking);
    cudaEvent_t eFork, eJoin;
    cudaEventCreateWithFlags(&eFork, cudaEventDisableTiming);
    cudaEventCreateWithFlags(&eJoin, cudaEventDisableTiming);

    cudaEventRecord(eFork, 0);
    cudaStreamWaitEvent(s2, eFork, 0);

    const int TB = 256;
    // ---- branch B (s2): deg+flags zero -> hist -> lookback scan
    cudaMemsetAsync(pdegflag, 0, (NN + NB) * sizeof(int), s2);
    hist_k<<<(T + TB - 1) / TB, TB, 0, s2>>>(edge, paper, author, E, Ep, Ea, T);
    scan_k<<<NB, 256, 0, s2>>>();
    cudaEventRecord(eJoin, s2);

    // ---- branch A (default): sc zero -> wvec -> merged input GEMM
    cudaMemsetAsync(psc, 0, 4 * NN * sizeof(float), 0);
    wvec_k<<<1, 128>>>(W1, a1s, a1d, W2, a2s, a2d);
    const int nbS = (NS + 63) / 64, nbT = (NT + 63) / 64;
    mma_gemm<<<nbS + nbT, 256, GEMM_SMEM>>>(
        x_s, Ws, bs, nullptr, NS, 0,
        x_t, Wt, bt, nullptr, NT, NS,
        nbS, 0, 1);

    // ---- join, then fill -> spmm -> merged output GEMM
    cudaStreamWaitEvent(0, eJoin, 0);
    fill_k<<<(T + TB - 1) / TB, TB>>>(edge, paper, author, E, Ep, Ea, T);
    spmm_k<<<(NN * 32 + TB - 1) / TB, TB>>>();
    mma_gemm<<<nbT + nbS, 256, GEMM_SMEM>>>(
        pagg + (size_t)NS * DD, W1, nullptr, out_t, NT, 0,
        pagg, W2, nullptr, out_s, NS, 0,
        nbT, 1, 0);
}

// round 16
// speedup vs baseline: 1.0199x; 1.0199x over previous
#include <cuda_runtime.h>
#include <cuda_fp16.h>
#include <cstdint>

#define NS 50000
#define NT 50000
#define NN 100000
#define DD 128
#define CAP 2200000
#define NB  ((NN + 255) / 256)
#define HS_GRID 444   // 148 SMs x 3 blocks: guaranteed co-resident for grid barrier

// ---------------- zeroed-every-launch state (ONE memset) --------------------------
// layout (ints): [0] bar_count, [1] bar_gen, [2..2+NB) lookback flags,
//                [512..512+NN) degree, [512+NN ..) scores (4*NN floats)
#define ZBAR  0
#define ZFLAG 2
#define ZDEG  512
#define ZSC   (512 + NN)
#define ZTOT  (512 + NN + 4 * NN)
static __device__ __align__(16) int g_z[ZTOT];

// ---------------- other scratch ----------------------------------------------------
static __device__ __half g_xh[NN * DD];   // transformed features, fp16 (gather source)
static __device__ float g_agg[NN * DD];   // rows [0,NS): conv2 agg; [NS,NN): conv1
static __device__ float g_wv [4 * DD];
static __device__ int   g_rowptr[NN];
static __device__ int   g_cur[NN];
static __device__ int   g_blk_agg[NB + 1];
static __device__ int   g_blk_pref[NB + 1];
static __device__ int2  g_epack[CAP];     // {src, w as float bits}

__device__ __forceinline__ float* zsc() { return (float*)(g_z + ZSC); }

#define MMA_F16(d, a0, a1, a2, a3, b0, b1)                                       \
    asm volatile("mma.sync.aligned.m16n8k16.row.col.f32.f16.f16.f32 "            \
        "{%0,%1,%2,%3}, {%4,%5,%6,%7}, {%8,%9}, {%0,%1,%2,%3};"                  \
        : "+f"((d)[0]), "+f"((d)[1]), "+f"((d)[2]), "+f"((d)[3])                 \
        : "r"(a0), "r"(a1), "r"(a2), "r"(a3), "r"(b0), "r"(b1))

#define LDSM_X4(r0, r1, r2, r3, addr)                                            \
    asm volatile("ldmatrix.sync.aligned.m8n8.x4.shared.b16 {%0,%1,%2,%3}, [%4];" \
        : "=r"(r0), "=r"(r1), "=r"(r2), "=r"(r3) : "r"(addr))

// =============== GEMM: C = A[M,128] @ W[128,128]^T, 1-pass fp16 + ldmatrix =======
#define PH 136
__global__ __launch_bounds__(256)
void mma_gemm(const float* __restrict__ A1, const float* __restrict__ W1p,
              const float* __restrict__ b1, float* __restrict__ C1, int M1, int so1,
              const float* __restrict__ A2, const float* __restrict__ W2p,
              const float* __restrict__ b2, float* __restrict__ C2, int M2, int so2,
              int nb1, int doRelu, int doScores)
{
    extern __shared__ __half sh[];
    __half* sA = sh;               // 64  x PH
    __half* sW = sh + 64 * PH;     // 128 x PH

    const float* A; const float* W; const float* bias; float* C;
    int M, scoreOff, row0;
    if (blockIdx.x < nb1) {
        A = A1; W = W1p; bias = b1; C = C1; M = M1; scoreOff = so1;
        row0 = blockIdx.x * 64;
    } else {
        A = A2; W = W2p; bias = b2; C = C2; M = M2; scoreOff = so2;
        row0 = (blockIdx.x - nb1) * 64;
    }
    const int tid = threadIdx.x;

    for (int i = tid; i < 4096; i += 256) {
        int n  = i >> 5;
        int k4 = (i & 31) << 2;
        float4 w = *(const float4*)(W + n * 128 + k4);
        uint2 p;
        *(__half2*)&p.x = __floats2half2_rn(w.x, w.y);
        *(__half2*)&p.y = __floats2half2_rn(w.z, w.w);
        *(uint2*)(sW + n * PH + k4) = p;
    }
    for (int i = tid; i < 2048; i += 256) {
        int r  = i >> 5;
        int k4 = (i & 31) << 2;
        int gr = row0 + r;
        float4 v = make_float4(0.f, 0.f, 0.f, 0.f);
        if (gr < M) v = *(const float4*)(A + (size_t)gr * 128 + k4);
        uint2 p;
        *(__half2*)&p.x = __floats2half2_rn(v.x, v.y);
        *(__half2*)&p.y = __floats2half2_rn(v.z, v.w);
        *(uint2*)(sA + r * PH + k4) = p;
    }
    __syncthreads();

    const int wid  = tid >> 5;
    const int lane = tid & 31;
    const int mw   = wid & 3;
    const int nb   = (wid >> 2) * 64;
    const int g    = lane >> 2;
    const int tq   = lane & 3;

    const int r8 = lane & 7;
    const int j  = lane >> 3;
    const uint32_t aBase = (uint32_t)__cvta_generic_to_shared(sA)
        + (uint32_t)(((mw * 16 + ((j & 1) << 3) + r8) * PH + ((j >> 1) << 3)) * 2);
    const uint32_t bBase = (uint32_t)__cvta_generic_to_shared(sW)
        + (uint32_t)(((nb + ((j >> 1) << 3) + r8) * PH + ((j & 1) << 3)) * 2);

    float acc[8][4] = {};

#pragma unroll
    for (int ks = 0; ks < 8; ks++) {
        uint32_t a0, a1, a2, a3;
        LDSM_X4(a0, a1, a2, a3, aBase + ks * 32);
        uint32_t b[16];
#pragma unroll
        for (int p = 0; p < 4; p++)
            LDSM_X4(b[p * 4], b[p * 4 + 1], b[p * 4 + 2], b[p * 4 + 3],
                    bBase + (uint32_t)(p * 16 * PH * 2) + ks * 32);
#pragma unroll
        for (int nt = 0; nt < 8; nt++)
            MMA_F16(acc[nt], a0, a1, a2, a3, b[nt * 2], b[nt * 2 + 1]);
    }

    const int r0 = row0 + mw * 16 + g;
    const int r1 = r0 + 8;
    float s0[4] = {}, s1[4] = {};

#pragma unroll
    for (int nt = 0; nt < 8; nt++) {
        int c = nb + nt * 8 + tq * 2;
        float bx = 0.f, by = 0.f;
        if (bias) { float2 b = *(const float2*)(bias + c); bx = b.x; by = b.y; }
        float o00 = acc[nt][0] + bx, o01 = acc[nt][1] + by;
        float o10 = acc[nt][2] + bx, o11 = acc[nt][3] + by;
        if (doScores) {
#pragma unroll
            for (int t = 0; t < 4; t++) {
                float2 w = *(const float2*)(g_wv + t * 128 + c);
                s0[t] += o00 * w.x + o01 * w.y;
                s1[t] += o10 * w.x + o11 * w.y;
            }
            if (r0 < M) *(__half2*)(g_xh + (size_t)(scoreOff + r0) * 128 + c) =
                __floats2half2_rn(o00, o01);
            if (r1 < M) *(__half2*)(g_xh + (size_t)(scoreOff + r1) * 128 + c) =
                __floats2half2_rn(o10, o11);
        } else {
            if (doRelu) {
                o00 = o00 > 0.f ? o00 : 0.f; o01 = o01 > 0.f ? o01 : 0.f;
                o10 = o10 > 0.f ? o10 : 0.f; o11 = o11 > 0.f ? o11 : 0.f;
            }
            if (r0 < M) *(float2*)(C + (size_t)r0 * 128 + c) = make_float2(o00, o01);
            if (r1 < M) *(float2*)(C + (size_t)r1 * 128 + c) = make_float2(o10, o11);
        }
    }

    if (doScores) {
        float* sc = zsc();
#pragma unroll
        for (int t = 0; t < 4; t++) {
            s0[t] += __shfl_xor_sync(0xFFFFFFFFu, s0[t], 1);
            s0[t] += __shfl_xor_sync(0xFFFFFFFFu, s0[t], 2);
            s1[t] += __shfl_xor_sync(0xFFFFFFFFu, s1[t], 1);
            s1[t] += __shfl_xor_sync(0xFFFFFFFFu, s1[t], 2);
        }
        if (tq == 0) {
#pragma unroll
            for (int t = 0; t < 4; t++) {
                if (r0 < M) atomicAdd(&sc[t * NN + scoreOff + r0], s0[t]);
                if (r1 < M) atomicAdd(&sc[t * NN + scoreOff + r1], s1[t]);
            }
        }
    }
}

// ---------------- precompute wv = W^T a (4 vectors of 128) -----------------------
__global__ void wvec_k(const float* __restrict__ W1, const float* __restrict__ a1s,
                       const float* __restrict__ a1d,
                       const float* __restrict__ W2, const float* __restrict__ a2s,
                       const float* __restrict__ a2d)
{
    int d = threadIdx.x;
    float s1 = 0.f, s2 = 0.f, s3 = 0.f, s4 = 0.f;
    for (int k = 0; k < 128; k++) {
        float w1 = W1[k * 128 + d], w2 = W2[k * 128 + d];
        s1 += w1 * a1s[k];
        s2 += w1 * a1d[k];
        s3 += w2 * a2s[k];
        s4 += w2 * a2d[k];
    }
    g_wv[d] = s1; g_wv[128 + d] = s2; g_wv[256 + d] = s3; g_wv[384 + d] = s4;
}

__device__ __forceinline__ float leaky(float e) { return e > 0.f ? e : 0.2f * e; }

// ---------------- combined edge decomposition ------------------------------------
__device__ __forceinline__ bool decomp_edge(int i, const int* edge, const int* paper,
                                            const int* author, int E, int Ep, int Ea,
                                            int& s, int& d, int& conv1)
{
    if (i < E) { s = edge[i]; d = edge[E + i] + NS; conv1 = 1; return true; }
    i -= E;
    if (i < Ea) { s = author[i]; d = author[Ea + i]; conv1 = 1; return d >= NS; }
    i -= Ea;
    if (i < NT) { s = d = NS + i; conv1 = 1; return true; }
    i -= NT;
    if (i < E) { s = edge[E + i] + NS; d = edge[i]; conv1 = 0; return true; }
    i -= E;
    if (i < Ep) { s = paper[i]; d = paper[Ep + i]; conv1 = 0; return d < NS; }
    i -= Ep;
    if (i < NS) { s = d = i; conv1 = 0; return true; }
    return false;
}

// ---------------- fused histogram + grid barrier + decoupled-lookback scan -------
__global__ __launch_bounds__(256)
void histscan_k(const int* __restrict__ edge, const int* __restrict__ paper,
                const int* __restrict__ author, int E, int Ep, int Ea, int T)
{
    // phase 1: degree histogram (grid-stride)
    const int stride = gridDim.x * blockDim.x;
    for (int i = blockIdx.x * blockDim.x + threadIdx.x; i < T; i += stride) {
        int s, d, c1;
        if (decomp_edge(i, edge, paper, author, E, Ep, Ea, s, d, c1))
            atomicAdd(&g_z[ZDEG + d], 1);
    }

    // grid barrier (all HS_GRID blocks are co-resident)
    __syncthreads();
    if (threadIdx.x == 0) {
        __threadfence();
        int c = atomicAdd(&g_z[ZBAR], 1);
        if (c == gridDim.x - 1) atomicExch(&g_z[ZBAR + 1], 1);
        else while (atomicAdd(&g_z[ZBAR + 1], 0) == 0) { }
    }
    __syncthreads();

    // phase 2: exclusive scan (blocks 0..NB-1)
    if (blockIdx.x >= NB) return;
    __shared__ int sm[256];
    __shared__ int s_prefix;
    int* flag = g_z + ZFLAG;
    const int b = blockIdx.x, t = threadIdx.x;
    const int i = b * 256 + t;
    int v = (i < NN) ? g_z[ZDEG + i] : 0;
    sm[t] = v; __syncthreads();
#pragma unroll
    for (int off = 1; off < 256; off <<= 1) {
        int u = (t >= off) ? sm[t - off] : 0;
        __syncthreads();
        sm[t] += u;
        __syncthreads();
    }
    int incl  = sm[t];
    int total = sm[255];

    if (t == 0) {
        g_blk_agg[b] = total;
        __threadfence();
        atomicExch(&flag[b], 1);
        int prefix = 0;
        for (int jj = b - 1; jj >= 0; ) {
            int f;
            do { f = atomicAdd(&flag[jj], 0); } while (f == 0);
            if (f == 2) { prefix += g_blk_pref[jj]; break; }
            prefix += g_blk_agg[jj];
            jj--;
        }
        g_blk_pref[b] = prefix + total;
        __threadfence();
        atomicExch(&flag[b], 2);
        s_prefix = prefix;
    }
    __syncthreads();
    if (i < NN) {
        int rp = s_prefix + incl - v;
        g_rowptr[i] = rp;
        g_cur[i]    = rp;
    }
}

__global__ void fill_k(const int* __restrict__ edge, const int* __restrict__ paper,
                       const int* __restrict__ author, int E, int Ep, int Ea, int T)
{
    int i = blockIdx.x * blockDim.x + threadIdx.x;
    if (i >= T) return;
    int s, d, c1;
    if (!decomp_edge(i, edge, paper, author, E, Ep, Ea, s, d, c1)) return;
    const float* sc = zsc();
    float e = c1 ? (sc[s] + sc[NN + d]) : (sc[2 * NN + s] + sc[3 * NN + d]);
    float w = __expf(leaky(e));
    int pos = atomicAdd(&g_cur[d], 1);
    if (pos < CAP) g_epack[pos] = make_int2(s, __float_as_int(w));
}

// ---------------- SpMM: warp per dst row, shfl-broadcast edges, ILP-4 gathers ----
__device__ __forceinline__ void gacc(float4& acc, float w, uint2 u)
{
    float2 f0 = __half22float2(*(__half2*)&u.x);
    float2 f1 = __half22float2(*(__half2*)&u.y);
    acc.x += w * f0.x; acc.y += w * f0.y;
    acc.z += w * f1.x; acc.w += w * f1.y;
}

__global__ __launch_bounds__(256)
void spmm_k()
{
    int r    = (blockIdx.x * blockDim.x + threadIdx.x) >> 5;
    int lane = threadIdx.x & 31;
    if (r >= NN) return;
    int start = g_rowptr[r];
    int n     = g_z[ZDEG + r];
    float4 acc = make_float4(0.f, 0.f, 0.f, 0.f);
    float  den = 0.f;

    for (int base = 0; base < n; base += 32) {
        int m = n - base; if (m > 32) m = 32;
        int   src = 0; float wv = 0.f;
        if (lane < m) {
            int2 p = g_epack[start + base + lane];
            src = p.x;
            wv  = __int_as_float(p.y);
        }
        int jj = 0;
        for (; jj + 4 <= m; jj += 4) {
            int   s0 = __shfl_sync(0xFFFFFFFFu, src, jj);
            int   s1 = __shfl_sync(0xFFFFFFFFu, src, jj + 1);
            int   s2 = __shfl_sync(0xFFFFFFFFu, src, jj + 2);
            int   s3 = __shfl_sync(0xFFFFFFFFu, src, jj + 3);
            float w0 = __shfl_sync(0xFFFFFFFFu, wv, jj);
            float w1 = __shfl_sync(0xFFFFFFFFu, wv, jj + 1);
            float w2 = __shfl_sync(0xFFFFFFFFu, wv, jj + 2);
            float w3 = __shfl_sync(0xFFFFFFFFu, wv, jj + 3);
            uint2 u0 = *(const uint2*)(g_xh + (size_t)s0 * 128 + lane * 4);
            uint2 u1 = *(const uint2*)(g_xh + (size_t)s1 * 128 + lane * 4);
            uint2 u2 = *(const uint2*)(g_xh + (size_t)s2 * 128 + lane * 4);
            uint2 u3 = *(const uint2*)(g_xh + (size_t)s3 * 128 + lane * 4);
            gacc(acc, w0, u0); gacc(acc, w1, u1);
            gacc(acc, w2, u2); gacc(acc, w3, u3);
            den += w0 + w1 + w2 + w3;
        }
        for (; jj < m; jj++) {
            int   s0 = __shfl_sync(0xFFFFFFFFu, src, jj);
            float w0 = __shfl_sync(0xFFFFFFFFu, wv, jj);
            uint2 u0 = *(const uint2*)(g_xh + (size_t)s0 * 128 + lane * 4);
            gacc(acc, w0, u0);
            den += w0;
        }
    }
    float rc = __frcp_rn(den + 1e-16f);
    acc.x *= rc; acc.y *= rc; acc.z *= rc; acc.w *= rc;
    *(float4*)(g_agg + (size_t)r * 128 + lane * 4) = acc;
}

// ---------------- host launch -----------------------------------------------------
extern "C" void kernel_launch(void* const* d_in, const int* in_sizes, int n_in,
                              void* d_out, int out_size)
{
    const int* edge   = (const int*)d_in[0];
    const int* paper  = (const int*)d_in[1];
    const int* author = (const int*)d_in[2];
    const float* x_s = (const float*)d_in[3];
    const float* x_t = (const float*)d_in[4];
    const float* Ws  = (const float*)d_in[5];
    const float* bs  = (const float*)d_in[6];
    const float* Wt  = (const float*)d_in[7];
    const float* bt  = (const float*)d_in[8];
    const float* W1  = (const float*)d_in[9];
    const float* a1s = (const float*)d_in[10];
    const float* a1d = (const float*)d_in[11];
    const float* W2  = (const float*)d_in[12];
    const float* a2s = (const float*)d_in[13];
    const float* a2d = (const float*)d_in[14];

    const int E  = in_sizes[0] / 2;
    const int Ep = in_sizes[1] / 2;
    const int Ea = in_sizes[2] / 2;
    const int T  = 2 * E + Ea + Ep + NS + NT;

    float* pagg;
    cudaGetSymbolAddress((void**)&pagg, g_agg);
    int* pz;
    cudaGetSymbolAddress((void**)&pz, g_z);

    float* out = (float*)d_out;
    float* out_s = out;                     // conv2 result rows [0, NS)
    float* out_t = out + (size_t)NS * DD;   // conv1 result rows [NS, NN)

    const int GEMM_SMEM = (64 * PH + 128 * PH) * 2;  // 52224 B -> 4 CTAs/SM
    cudaFuncSetAttribute((const void*)mma_gemm,
                         cudaFuncAttributeMaxDynamicSharedMemorySize, GEMM_SMEM);

    cudaStream_t s2;
    cudaStreamCreateWithFlags(&s2, cudaStreamNonBlocking);
    cudaEvent_t eFork, eJoin;
    cudaEventCreateWithFlags(&eFork, cudaEventDisableTiming);
    cudaEventCreateWithFlags(&eJoin, cudaEventDisableTiming);

    const int TB = 256;

    // single memset: barrier state + lookback flags + degree + scores
    cudaMemsetAsync(pz, 0, ZTOT * sizeof(int), 0);

    cudaEventRecord(eFork, 0);
    cudaStreamWaitEvent(s2, eFork, 0);

    // ---- branch B (s2): fused hist + grid-barrier + scan
    histscan_k<<<HS_GRID, 256, 0, s2>>>(edge, paper, author, E, Ep, Ea, T);
    cudaEventRecord(eJoin, s2);

    // ---- branch A (default): wvec -> merged input GEMM (fp16 x + fused scores)
    wvec_k<<<1, 128>>>(W1, a1s, a1d, W2, a2s, a2d);
    const int nbS = (NS + 63) / 64, nbT = (NT + 63) / 64;
    mma_gemm<<<nbS + nbT, 256, GEMM_SMEM>>>(
        x_s, Ws, bs, nullptr, NS, 0,
        x_t, Wt, bt, nullptr, NT, NS,
        nbS, 0, 1);

    // ---- join, then fill -> spmm -> merged output GEMM
    cudaStreamWaitEvent(0, eJoin, 0);
    fill_k<<<(T + TB - 1) / TB, TB>>>(edge, paper, author, E, Ep, Ea, T);
    spmm_k<<<(NN * 32 + TB - 1) / TB, TB>>>();
    mma_gemm<<<nbT + nbS, 256, GEMM_SMEM>>>(
        pagg + (size_t)NS * DD, W1, nullptr, out_t, NT, 0,
        pagg, W2, nullptr, out_s, NS, 0,
        nbT, 1, 0);
}